// round 10
// baseline (speedup 1.0000x reference)
#include <cuda_runtime.h>
#include <cstdint>

#define LTOK 49
#define CDIM 256
#define NHEAD 8

#define MAXWIN 4096
#define MAXM (MAXWIN * LTOK)          // 200704
#define MAXNW 64
#define LL (LTOK * LTOK)              // 2401
#define BMSTR 50
#define BMLL (LTOK * BMSTR)           // 2450

// ---------------- scratch (device globals) ----------------
__device__ alignas(256) float g_xt[(size_t)MAXM * CDIM];   // tf32-rounded x
__device__ alignas(256) float g_qkv[(size_t)MAXM * 768];   // Q|K|V (tf32-rounded)
__device__ alignas(256) float g_attn[(size_t)MAXM * CDIM]; // attn out (tf32-rounded)
__device__ alignas(256) float g_wqkv[256 * 768];           // packed, rounded
__device__ alignas(256) float g_wo[256 * 256];             // rounded
__device__ alignas(256) float g_bm[(size_t)MAXNW * NHEAD * BMLL];

// ---------------- helpers ----------------
__device__ __forceinline__ uint32_t f2tf32(float f) {
    uint32_t u;
    asm("cvt.rna.tf32.f32 %0, %1;" : "=r"(u) : "f"(f));
    return u;
}

__device__ __forceinline__ void mma_tf32(float acc[4], uint32_t a0, uint32_t a1,
                                         uint32_t a2, uint32_t a3,
                                         uint32_t b0, uint32_t b1) {
    asm volatile(
        "mma.sync.aligned.m16n8k8.row.col.f32.tf32.tf32.f32 "
        "{%0,%1,%2,%3}, {%4,%5,%6,%7}, {%8,%9}, {%0,%1,%2,%3};"
        : "+f"(acc[0]), "+f"(acc[1]), "+f"(acc[2]), "+f"(acc[3])
        : "r"(a0), "r"(a1), "r"(a2), "r"(a3), "r"(b0), "r"(b1));
}

__device__ __forceinline__ uint32_t smem_u32(const void* p) {
    return (uint32_t)__cvta_generic_to_shared(p);
}
#define CPASYNC16(dst, src) \
    asm volatile("cp.async.ca.shared.global [%0], [%1], 16;" :: "r"(dst), "l"(src))

// FMA-only exp (no MUFU)
__device__ __forceinline__ float fastexp(float x) {
    x = fmaxf(x, -80.f);
    const float LOG2E = 1.4426950408889634f;
    const float MAGIC = 12582912.f;            // 1.5 * 2^23
    float z = fmaf(x, LOG2E, MAGIC);
    float f = fmaf(x, LOG2E, MAGIC - z);
    float p = 0.0013333558f;
    p = fmaf(p, f, 0.0096181291f);
    p = fmaf(p, f, 0.0555041087f);
    p = fmaf(p, f, 0.2402265069f);
    p = fmaf(p, f, 0.6931471806f);
    p = fmaf(p, f, 1.0f);
    return __int_as_float(__float_as_int(p) + (__float_as_int(z) << 23));
}

__device__ __forceinline__ uint4 round4(float4 v) {
    uint4 u;
    u.x = f2tf32(v.x); u.y = f2tf32(v.y);
    u.z = f2tf32(v.z); u.w = f2tf32(v.w);
    return u;
}

// ---------------- x -> tf32-rounded copy ----------------
__global__ void cvt_x_kernel(const float* __restrict__ x) {
    const size_t i = (size_t)blockIdx.x * 256 + threadIdx.x;  // float4 index
    ((uint4*)g_xt)[i] = round4(((const float4*)x)[i]);
}

// ---------------- weight pack (rounded): wqkv (blocks 0..63) + wo (64..127) --
__global__ void pack_w_kernel(const float* __restrict__ wq,
                              const float* __restrict__ wk,
                              const float* __restrict__ wv,
                              const float* __restrict__ wo) {
    const int b = blockIdx.x;
    if (b < 64) {
        const int i = b * 256 + threadIdx.x;          // 0..16383 float4
        const int k = i >> 6, c4 = i & 63;
        uint4* dst = (uint4*)(g_wqkv + (size_t)k * 768);
        dst[c4]       = round4(((const float4*)wq)[i]);
        dst[64 + c4]  = round4(((const float4*)wk)[i]);
        dst[128 + c4] = round4(((const float4*)wv)[i]);
    } else {
        const int i = (b - 64) * 256 + threadIdx.x;   // 0..16383 float4 (FIXED: 64 blocks)
        ((uint4*)g_wo)[i] = round4(((const float4*)wo)[i]);
    }
}

// ---------------- bias+mask fuse ----------------
__global__ void bm_kernel(const float* __restrict__ mask,
                          const float* __restrict__ bias_table,
                          const int* __restrict__ rel_index) {
    const int w = blockIdx.x, h = blockIdx.y;
    const float* mp = mask + (size_t)w * LL;
    float* dst = g_bm + ((size_t)w * NHEAD + h) * BMLL;
    for (int e = threadIdx.x; e < BMLL; e += 256) {
        const int i = e / BMSTR, j = e % BMSTR;
        dst[e] = (j < LTOK) ? bias_table[rel_index[i * LTOK + j] * NHEAD + h]
                              + mp[i * LTOK + j]
                            : 0.f;
    }
}

// ---------------- GEMM: cp.async 2-stage, inputs pre-rounded ----------------
// C[M,N] = A[M,256] @ W[256,N]. Requires M % 128 == 0 (M = 200704 = 128*1568).
#define BM 128
#define BN 128
#define BK 32
#define ASTR 36
#define BSTR 136
#define NKC 8       // 256 / BK
#define A_FLOATS (BM * ASTR)   // 4608
#define B_FLOATS (BK * BSTR)   // 4352
#define SMEM_GEMM ((2 * (A_FLOATS + B_FLOATS)) * 4)   // 71,680 B

template<bool ROUND_C>
__global__ void __launch_bounds__(256, 2)
gemm_cp_kernel(const float* __restrict__ A, const float* __restrict__ W,
               float* __restrict__ C, int M, int lda, int ldw, int ldc)
{
    extern __shared__ __align__(16) float sm[];
    float* As[2] = { sm,                      sm + A_FLOATS };
    float* Bs[2] = { sm + 2 * A_FLOATS,       sm + 2 * A_FLOATS + B_FLOATS };

    const int bn = blockIdx.x;
    const int bm = blockIdx.y;
    const int tid = threadIdx.x;
    const int lane = tid & 31, warp = tid >> 5;
    const int wm = warp >> 2, wn = warp & 3;
    const int g = lane >> 2, t = lane & 3;

    const float* Ab = A + (size_t)bm * BM * lda;
    const float* Wb = W + (size_t)bn * BN;

    const int ar[4] = { (tid) >> 3, (tid + 256) >> 3, (tid + 512) >> 3, (tid + 768) >> 3 };
    const int ac = (tid & 7) * 4;
    const int br[4] = { (tid) >> 5, (tid + 256) >> 5, (tid + 512) >> 5, (tid + 768) >> 5 };
    const int bc = (tid & 31) * 4;

    uint32_t adst[2][4], bdst[2][4];
#pragma unroll
    for (int s = 0; s < 2; ++s)
#pragma unroll
        for (int it = 0; it < 4; ++it) {
            adst[s][it] = smem_u32(&As[s][ar[it] * ASTR + ac]);
            bdst[s][it] = smem_u32(&Bs[s][br[it] * BSTR + bc]);
        }

    float acc[4][4][4];
#pragma unroll
    for (int mi = 0; mi < 4; ++mi)
#pragma unroll
        for (int ni = 0; ni < 4; ++ni)
#pragma unroll
            for (int q = 0; q < 4; ++q) acc[mi][ni][q] = 0.f;

    // prologue: stage kc=0 into buffer 0
#pragma unroll
    for (int it = 0; it < 4; ++it)
        CPASYNC16(adst[0][it], Ab + (size_t)ar[it] * lda + ac);
#pragma unroll
    for (int it = 0; it < 4; ++it)
        CPASYNC16(bdst[0][it], Wb + (size_t)br[it] * ldw + bc);
    asm volatile("cp.async.commit_group;" ::: "memory");

    for (int i = 0; i < NKC; ++i) {
        const int s = i & 1;
        if (i + 1 < NKC) {
            const int kc = (i + 1) * BK;
            const int s1 = s ^ 1;
#pragma unroll
            for (int it = 0; it < 4; ++it)
                CPASYNC16(adst[s1][it], Ab + (size_t)ar[it] * lda + kc + ac);
#pragma unroll
            for (int it = 0; it < 4; ++it)
                CPASYNC16(bdst[s1][it], Wb + (size_t)(kc + br[it]) * ldw + bc);
            asm volatile("cp.async.commit_group;" ::: "memory");
            asm volatile("cp.async.wait_group 1;" ::: "memory");
        } else {
            asm volatile("cp.async.wait_group 0;" ::: "memory");
        }
        __syncthreads();

        const float* Asb = As[s];
        const float* Bsb = Bs[s];
#pragma unroll
        for (int kk = 0; kk < BK; kk += 8) {
            uint32_t a[4][4];
#pragma unroll
            for (int mi = 0; mi < 4; ++mi) {
                const float* ap = &Asb[(wm * 64 + mi * 16 + g) * ASTR + kk + t];
                a[mi][0] = __float_as_uint(ap[0]);
                a[mi][2] = __float_as_uint(ap[4]);
                a[mi][1] = __float_as_uint(ap[8 * ASTR]);
                a[mi][3] = __float_as_uint(ap[8 * ASTR + 4]);
            }
            uint32_t b[4][2];
#pragma unroll
            for (int ni = 0; ni < 4; ++ni) {
                const float* bp = &Bsb[(kk + t) * BSTR + wn * 32 + ni * 8 + g];
                b[ni][0] = __float_as_uint(bp[0]);
                b[ni][1] = __float_as_uint(bp[4 * BSTR]);
            }
#pragma unroll
            for (int mi = 0; mi < 4; ++mi)
#pragma unroll
                for (int ni = 0; ni < 4; ++ni)
                    mma_tf32(acc[mi][ni], a[mi][0], a[mi][1], a[mi][2], a[mi][3],
                             b[ni][0], b[ni][1]);
        }
        __syncthreads();   // all reads of buf s done before it is refilled
    }

#pragma unroll
    for (int mi = 0; mi < 4; ++mi) {
        const int r0 = bm * BM + wm * 64 + mi * 16 + g;
#pragma unroll
        for (int ni = 0; ni < 4; ++ni) {
            const int col = bn * BN + wn * 32 + ni * 8 + 2 * t;
            float2 v0 = make_float2(acc[mi][ni][0], acc[mi][ni][1]);
            float2 v1 = make_float2(acc[mi][ni][2], acc[mi][ni][3]);
            if (ROUND_C) {
                v0.x = __uint_as_float(f2tf32(v0.x));
                v0.y = __uint_as_float(f2tf32(v0.y));
                v1.x = __uint_as_float(f2tf32(v1.x));
                v1.y = __uint_as_float(f2tf32(v1.y));
            }
            *(float2*)&C[(size_t)r0 * ldc + col] = v0;
            *(float2*)&C[(size_t)(r0 + 8) * ldc + col] = v1;
        }
    }
}

// ---------------- attention: tensor-core, K frags register-resident ---------
__global__ void __launch_bounds__(256, 2)
attn_kernel(int nw)
{
    const int n = blockIdx.x;
    const int h = threadIdx.x >> 5;
    const int lane = threadIdx.x & 31;
    const int g = lane >> 2, t = lane & 3;

    const float* qbase = g_qkv + (size_t)n * LTOK * 768 + h * 32;
    const float* kbase = qbase + 256;
    const float* vbase = qbase + 512;
    const float* bmp = g_bm + ((size_t)(n % nw) * NHEAD + h) * BMLL;

    const int sl0 = (lane & ~3) | (t >> 1);
    const int sl2 = sl0 + 2;
    const bool todd = (t & 1);

    // ---- hoist K fragments: loaded once, reused by all 4 mi tiles ----
    uint32_t kf[4][7][2];
#pragma unroll
    for (int ni = 0; ni < 7; ++ni) {
        int kr = 8 * ni + g; if (kr > 48) kr = 48;
        const float* kp = kbase + (size_t)kr * 768;
#pragma unroll
        for (int k = 0; k < 4; ++k) {
            kf[k][ni][0] = __float_as_uint(kp[8 * k + t]);
            kf[k][ni][1] = __float_as_uint(kp[8 * k + t + 4]);
        }
    }

#pragma unroll
    for (int mi = 0; mi < 4; ++mi) {
        const int r0 = 16 * mi + g;
        const int r1 = r0 + 8;
        const int r0c = r0 < 48 ? r0 : 48;
        const int r1c = r1 < 48 ? r1 : 48;
        const float* qr0 = qbase + (size_t)r0c * 768;
        const float* qr1 = qbase + (size_t)r1c * 768;

        // ---- S = Q K^T ----
        float S[7][4];
#pragma unroll
        for (int ni = 0; ni < 7; ++ni) {
            S[ni][0] = 0.f; S[ni][1] = 0.f; S[ni][2] = 0.f; S[ni][3] = 0.f;
        }
#pragma unroll
        for (int k = 0; k < 4; ++k) {
            const int kk = 8 * k;
            const uint32_t a0 = __float_as_uint(qr0[kk + t]);
            const uint32_t a1 = __float_as_uint(qr1[kk + t]);
            const uint32_t a2 = __float_as_uint(qr0[kk + t + 4]);
            const uint32_t a3 = __float_as_uint(qr1[kk + t + 4]);
#pragma unroll
            for (int ni = 0; ni < 7; ++ni)
                mma_tf32(S[ni], a0, a1, a2, a3, kf[k][ni][0], kf[k][ni][1]);
        }

        // ---- softmax in C-fragments ----
        float sum0 = 0.f, sum1 = 0.f;
        const float* bm0 = bmp + r0c * BMSTR;
        const float* bm1 = bmp + r1c * BMSTR;
#pragma unroll
        for (int ni = 0; ni < 7; ++ni) {
            const int c = 8 * ni + 2 * t;
            const float2 m0 = *(const float2*)(bm0 + c);
            const float2 m1 = *(const float2*)(bm1 + c);
            float e0 = 0.f, e1 = 0.f, e2 = 0.f, e3 = 0.f;
            if (c < LTOK)     { e0 = fastexp(S[ni][0] + m0.x); e2 = fastexp(S[ni][2] + m1.x); }
            if (c + 1 < LTOK) { e1 = fastexp(S[ni][1] + m0.y); e3 = fastexp(S[ni][3] + m1.y); }
            S[ni][0] = e0; S[ni][1] = e1; S[ni][2] = e2; S[ni][3] = e3;
            sum0 += e0 + e1; sum1 += e2 + e3;
        }
        sum0 += __shfl_xor_sync(0xffffffffu, sum0, 1);
        sum0 += __shfl_xor_sync(0xffffffffu, sum0, 2);
        sum1 += __shfl_xor_sync(0xffffffffu, sum1, 1);
        sum1 += __shfl_xor_sync(0xffffffffu, sum1, 2);
        const float inv0 = 1.f / sum0, inv1 = 1.f / sum1;

#pragma unroll
        for (int ni = 0; ni < 7; ++ni) {
            S[ni][0] = __uint_as_float(f2tf32(S[ni][0] * inv0));
            S[ni][1] = __uint_as_float(f2tf32(S[ni][1] * inv0));
            S[ni][2] = __uint_as_float(f2tf32(S[ni][2] * inv1));
            S[ni][3] = __uint_as_float(f2tf32(S[ni][3] * inv1));
        }

        // ---- O = P V ----
        float O[4][4];
#pragma unroll
        for (int nv = 0; nv < 4; ++nv) {
            O[nv][0] = 0.f; O[nv][1] = 0.f; O[nv][2] = 0.f; O[nv][3] = 0.f;
        }
#pragma unroll
        for (int kt = 0; kt < 7; ++kt) {
            const float v00 = __shfl_sync(0xffffffffu, S[kt][0], sl0);
            const float v01 = __shfl_sync(0xffffffffu, S[kt][1], sl0);
            const float v20 = __shfl_sync(0xffffffffu, S[kt][0], sl2);
            const float v21 = __shfl_sync(0xffffffffu, S[kt][1], sl2);
            const float v10 = __shfl_sync(0xffffffffu, S[kt][2], sl0);
            const float v11 = __shfl_sync(0xffffffffu, S[kt][3], sl0);
            const float v30 = __shfl_sync(0xffffffffu, S[kt][2], sl2);
            const float v31 = __shfl_sync(0xffffffffu, S[kt][3], sl2);
            const uint32_t a0 = __float_as_uint(todd ? v01 : v00);
            const uint32_t a2 = __float_as_uint(todd ? v21 : v20);
            const uint32_t a1 = __float_as_uint(todd ? v11 : v10);
            const uint32_t a3 = __float_as_uint(todd ? v31 : v30);

            int vr0 = 8 * kt + t;     if (vr0 > 48) vr0 = 48;
            int vr1 = 8 * kt + t + 4; if (vr1 > 48) vr1 = 48;
            const float* vp0 = vbase + (size_t)vr0 * 768;
            const float* vp1 = vbase + (size_t)vr1 * 768;
#pragma unroll
            for (int nv = 0; nv < 4; ++nv) {
                const uint32_t b0 = __float_as_uint(vp0[8 * nv + g]);
                const uint32_t b1 = __float_as_uint(vp1[8 * nv + g]);
                mma_tf32(O[nv], a0, a1, a2, a3, b0, b1);
            }
        }

        // ---- store O rounded (feeds GEMM2 as pre-rounded A) ----
        float* orow0 = g_attn + ((size_t)n * LTOK + r0) * CDIM + h * 32;
        float* orow1 = g_attn + ((size_t)n * LTOK + r1) * CDIM + h * 32;
#pragma unroll
        for (int nv = 0; nv < 4; ++nv) {
            const int c = 8 * nv + 2 * t;
            if (r0 < LTOK)
                *(float2*)(orow0 + c) = make_float2(__uint_as_float(f2tf32(O[nv][0])),
                                                    __uint_as_float(f2tf32(O[nv][1])));
            if (r1 < LTOK)
                *(float2*)(orow1 + c) = make_float2(__uint_as_float(f2tf32(O[nv][2])),
                                                    __uint_as_float(f2tf32(O[nv][3])));
        }
    }
}

// ---------------- launch ----------------
extern "C" void kernel_launch(void* const* d_in, const int* in_sizes, int n_in,
                              void* d_out, int out_size)
{
    const float* x    = (const float*)d_in[0];
    const float* mask = (const float*)d_in[1];
    const float* wq   = (const float*)d_in[2];
    const float* wk   = (const float*)d_in[3];
    const float* wv   = (const float*)d_in[4];
    const float* wo   = (const float*)d_in[5];
    const float* bt   = (const float*)d_in[6];
    const int*   ri   = (const int*)d_in[7];
    float* out = (float*)d_out;

    const int nwin = in_sizes[0] / (LTOK * CDIM);   // 4096
    const int nw   = in_sizes[1] / (LTOK * LTOK);   // 64
    const int M    = nwin * LTOK;                   // 200704 (mult of 128)

    float *xt, *qkv, *attn, *wqkv, *wop;
    cudaGetSymbolAddress((void**)&xt,   g_xt);
    cudaGetSymbolAddress((void**)&qkv,  g_qkv);
    cudaGetSymbolAddress((void**)&attn, g_attn);
    cudaGetSymbolAddress((void**)&wqkv, g_wqkv);
    cudaGetSymbolAddress((void**)&wop,  g_wo);

    cudaFuncSetAttribute((const void*)gemm_cp_kernel<true>,
                         cudaFuncAttributeMaxDynamicSharedMemorySize, SMEM_GEMM);
    cudaFuncSetAttribute((const void*)gemm_cp_kernel<false>,
                         cudaFuncAttributeMaxDynamicSharedMemorySize, SMEM_GEMM);

    // 1) pre-round inputs + fuse bias/mask
    cvt_x_kernel<<<(M * CDIM / 4) / 256, 256>>>(x);
    pack_w_kernel<<<128, 256>>>(wq, wk, wv, wo);   // FIXED: 64 wqkv + 64 wo blocks
    dim3 gb(nw, NHEAD);
    bm_kernel<<<gb, 256>>>(mask, bt, ri);

    // 2) QKV projection (rounded output)
    dim3 g1(768 / BN, M / BM);
    gemm_cp_kernel<true><<<g1, 256, SMEM_GEMM>>>(xt, wqkv, qkv, M, 256, 768, 768);

    // 3) attention
    attn_kernel<<<nwin, 256>>>(nw);

    // 4) output projection (fp32 output)
    dim3 g3(256 / BN, M / BM);
    gemm_cp_kernel<false><<<g3, 256, SMEM_GEMM>>>(attn, wop, out, M, 256, 256, 256);
}

// round 11
// speedup vs baseline: 1.0001x; 1.0001x over previous
#include <cuda_runtime.h>
#include <cstdint>

#define LTOK 49
#define CDIM 256
#define NHEAD 8

#define MAXWIN 4096
#define MAXM (MAXWIN * LTOK)          // 200704
#define MAXNW 64
#define LL (LTOK * LTOK)              // 2401
#define BMSTR 50
#define BMLL (LTOK * BMSTR)           // 2450

// ---------------- scratch (device globals) ----------------
__device__ alignas(256) float g_xt[(size_t)MAXM * CDIM];   // tf32-rounded x
__device__ alignas(256) float g_qkv[(size_t)MAXM * 768];   // Q|K|V (tf32-rounded)
__device__ alignas(256) float g_attn[(size_t)MAXM * CDIM]; // attn out (tf32-rounded)
__device__ alignas(256) float g_wqkv[256 * 768];           // packed, rounded
__device__ alignas(256) float g_wo[256 * 256];             // rounded
__device__ alignas(256) float g_bm[(size_t)MAXNW * NHEAD * BMLL];

// ---------------- helpers ----------------
__device__ __forceinline__ uint32_t f2tf32(float f) {
    uint32_t u;
    asm("cvt.rna.tf32.f32 %0, %1;" : "=r"(u) : "f"(f));
    return u;
}

__device__ __forceinline__ void mma_tf32(float acc[4], uint32_t a0, uint32_t a1,
                                         uint32_t a2, uint32_t a3,
                                         uint32_t b0, uint32_t b1) {
    asm volatile(
        "mma.sync.aligned.m16n8k8.row.col.f32.tf32.tf32.f32 "
        "{%0,%1,%2,%3}, {%4,%5,%6,%7}, {%8,%9}, {%0,%1,%2,%3};"
        : "+f"(acc[0]), "+f"(acc[1]), "+f"(acc[2]), "+f"(acc[3])
        : "r"(a0), "r"(a1), "r"(a2), "r"(a3), "r"(b0), "r"(b1));
}

__device__ __forceinline__ uint32_t smem_u32(const void* p) {
    return (uint32_t)__cvta_generic_to_shared(p);
}
#define CPASYNC16(dst, src) \
    asm volatile("cp.async.ca.shared.global [%0], [%1], 16;" :: "r"(dst), "l"(src))

// FMA-only exp (no MUFU)
__device__ __forceinline__ float fastexp(float x) {
    x = fmaxf(x, -80.f);
    const float LOG2E = 1.4426950408889634f;
    const float MAGIC = 12582912.f;            // 1.5 * 2^23
    float z = fmaf(x, LOG2E, MAGIC);
    float f = fmaf(x, LOG2E, MAGIC - z);
    float p = 0.0013333558f;
    p = fmaf(p, f, 0.0096181291f);
    p = fmaf(p, f, 0.0555041087f);
    p = fmaf(p, f, 0.2402265069f);
    p = fmaf(p, f, 0.6931471806f);
    p = fmaf(p, f, 1.0f);
    return __int_as_float(__float_as_int(p) + (__float_as_int(z) << 23));
}

__device__ __forceinline__ uint4 round4(float4 v) {
    uint4 u;
    u.x = f2tf32(v.x); u.y = f2tf32(v.y);
    u.z = f2tf32(v.z); u.w = f2tf32(v.w);
    return u;
}

// ---------------- x -> tf32-rounded copy ----------------
__global__ void cvt_x_kernel(const float* __restrict__ x) {
    const size_t i = (size_t)blockIdx.x * 256 + threadIdx.x;  // float4 index
    ((uint4*)g_xt)[i] = round4(((const float4*)x)[i]);
}

// ---------------- weight pack (rounded): wqkv (blocks 0..63) + wo (64..127) --
__global__ void pack_w_kernel(const float* __restrict__ wq,
                              const float* __restrict__ wk,
                              const float* __restrict__ wv,
                              const float* __restrict__ wo) {
    const int b = blockIdx.x;
    if (b < 64) {
        const int i = b * 256 + threadIdx.x;          // 0..16383 float4
        const int k = i >> 6, c4 = i & 63;
        uint4* dst = (uint4*)(g_wqkv + (size_t)k * 768);
        dst[c4]       = round4(((const float4*)wq)[i]);
        dst[64 + c4]  = round4(((const float4*)wk)[i]);
        dst[128 + c4] = round4(((const float4*)wv)[i]);
    } else {
        const int i = (b - 64) * 256 + threadIdx.x;   // 0..16383 float4 (FIXED: 64 blocks)
        ((uint4*)g_wo)[i] = round4(((const float4*)wo)[i]);
    }
}

// ---------------- bias+mask fuse ----------------
__global__ void bm_kernel(const float* __restrict__ mask,
                          const float* __restrict__ bias_table,
                          const int* __restrict__ rel_index) {
    const int w = blockIdx.x, h = blockIdx.y;
    const float* mp = mask + (size_t)w * LL;
    float* dst = g_bm + ((size_t)w * NHEAD + h) * BMLL;
    for (int e = threadIdx.x; e < BMLL; e += 256) {
        const int i = e / BMSTR, j = e % BMSTR;
        dst[e] = (j < LTOK) ? bias_table[rel_index[i * LTOK + j] * NHEAD + h]
                              + mp[i * LTOK + j]
                            : 0.f;
    }
}

// ---------------- GEMM: cp.async 2-stage, inputs pre-rounded ----------------
// C[M,N] = A[M,256] @ W[256,N]. Requires M % 128 == 0 (M = 200704 = 128*1568).
#define BM 128
#define BN 128
#define BK 32
#define ASTR 36
#define BSTR 136
#define NKC 8       // 256 / BK
#define A_FLOATS (BM * ASTR)   // 4608
#define B_FLOATS (BK * BSTR)   // 4352
#define SMEM_GEMM ((2 * (A_FLOATS + B_FLOATS)) * 4)   // 71,680 B

template<bool ROUND_C>
__global__ void __launch_bounds__(256, 2)
gemm_cp_kernel(const float* __restrict__ A, const float* __restrict__ W,
               float* __restrict__ C, int M, int lda, int ldw, int ldc)
{
    extern __shared__ __align__(16) float sm[];
    float* As[2] = { sm,                      sm + A_FLOATS };
    float* Bs[2] = { sm + 2 * A_FLOATS,       sm + 2 * A_FLOATS + B_FLOATS };

    const int bn = blockIdx.x;
    const int bm = blockIdx.y;
    const int tid = threadIdx.x;
    const int lane = tid & 31, warp = tid >> 5;
    const int wm = warp >> 2, wn = warp & 3;
    const int g = lane >> 2, t = lane & 3;

    const float* Ab = A + (size_t)bm * BM * lda;
    const float* Wb = W + (size_t)bn * BN;

    const int ar[4] = { (tid) >> 3, (tid + 256) >> 3, (tid + 512) >> 3, (tid + 768) >> 3 };
    const int ac = (tid & 7) * 4;
    const int br[4] = { (tid) >> 5, (tid + 256) >> 5, (tid + 512) >> 5, (tid + 768) >> 5 };
    const int bc = (tid & 31) * 4;

    uint32_t adst[2][4], bdst[2][4];
#pragma unroll
    for (int s = 0; s < 2; ++s)
#pragma unroll
        for (int it = 0; it < 4; ++it) {
            adst[s][it] = smem_u32(&As[s][ar[it] * ASTR + ac]);
            bdst[s][it] = smem_u32(&Bs[s][br[it] * BSTR + bc]);
        }

    float acc[4][4][4];
#pragma unroll
    for (int mi = 0; mi < 4; ++mi)
#pragma unroll
        for (int ni = 0; ni < 4; ++ni)
#pragma unroll
            for (int q = 0; q < 4; ++q) acc[mi][ni][q] = 0.f;

    // prologue: stage kc=0 into buffer 0
#pragma unroll
    for (int it = 0; it < 4; ++it)
        CPASYNC16(adst[0][it], Ab + (size_t)ar[it] * lda + ac);
#pragma unroll
    for (int it = 0; it < 4; ++it)
        CPASYNC16(bdst[0][it], Wb + (size_t)br[it] * ldw + bc);
    asm volatile("cp.async.commit_group;" ::: "memory");

    for (int i = 0; i < NKC; ++i) {
        const int s = i & 1;
        if (i + 1 < NKC) {
            const int kc = (i + 1) * BK;
            const int s1 = s ^ 1;
#pragma unroll
            for (int it = 0; it < 4; ++it)
                CPASYNC16(adst[s1][it], Ab + (size_t)ar[it] * lda + kc + ac);
#pragma unroll
            for (int it = 0; it < 4; ++it)
                CPASYNC16(bdst[s1][it], Wb + (size_t)(kc + br[it]) * ldw + bc);
            asm volatile("cp.async.commit_group;" ::: "memory");
            asm volatile("cp.async.wait_group 1;" ::: "memory");
        } else {
            asm volatile("cp.async.wait_group 0;" ::: "memory");
        }
        __syncthreads();

        const float* Asb = As[s];
        const float* Bsb = Bs[s];
#pragma unroll
        for (int kk = 0; kk < BK; kk += 8) {
            uint32_t a[4][4];
#pragma unroll
            for (int mi = 0; mi < 4; ++mi) {
                const float* ap = &Asb[(wm * 64 + mi * 16 + g) * ASTR + kk + t];
                a[mi][0] = __float_as_uint(ap[0]);
                a[mi][2] = __float_as_uint(ap[4]);
                a[mi][1] = __float_as_uint(ap[8 * ASTR]);
                a[mi][3] = __float_as_uint(ap[8 * ASTR + 4]);
            }
            uint32_t b[4][2];
#pragma unroll
            for (int ni = 0; ni < 4; ++ni) {
                const float* bp = &Bsb[(kk + t) * BSTR + wn * 32 + ni * 8 + g];
                b[ni][0] = __float_as_uint(bp[0]);
                b[ni][1] = __float_as_uint(bp[4 * BSTR]);
            }
#pragma unroll
            for (int mi = 0; mi < 4; ++mi)
#pragma unroll
                for (int ni = 0; ni < 4; ++ni)
                    mma_tf32(acc[mi][ni], a[mi][0], a[mi][1], a[mi][2], a[mi][3],
                             b[ni][0], b[ni][1]);
        }
        __syncthreads();   // all reads of buf s done before it is refilled
    }

#pragma unroll
    for (int mi = 0; mi < 4; ++mi) {
        const int r0 = bm * BM + wm * 64 + mi * 16 + g;
#pragma unroll
        for (int ni = 0; ni < 4; ++ni) {
            const int col = bn * BN + wn * 32 + ni * 8 + 2 * t;
            float2 v0 = make_float2(acc[mi][ni][0], acc[mi][ni][1]);
            float2 v1 = make_float2(acc[mi][ni][2], acc[mi][ni][3]);
            if (ROUND_C) {
                v0.x = __uint_as_float(f2tf32(v0.x));
                v0.y = __uint_as_float(f2tf32(v0.y));
                v1.x = __uint_as_float(f2tf32(v1.x));
                v1.y = __uint_as_float(f2tf32(v1.y));
            }
            *(float2*)&C[(size_t)r0 * ldc + col] = v0;
            *(float2*)&C[(size_t)(r0 + 8) * ldc + col] = v1;
        }
    }
}

// ---------------- attention: tensor-core, K frags register-resident ---------
__global__ void __launch_bounds__(256, 2)
attn_kernel(int nw)
{
    const int n = blockIdx.x;
    const int h = threadIdx.x >> 5;
    const int lane = threadIdx.x & 31;
    const int g = lane >> 2, t = lane & 3;

    const float* qbase = g_qkv + (size_t)n * LTOK * 768 + h * 32;
    const float* kbase = qbase + 256;
    const float* vbase = qbase + 512;
    const float* bmp = g_bm + ((size_t)(n % nw) * NHEAD + h) * BMLL;

    const int sl0 = (lane & ~3) | (t >> 1);
    const int sl2 = sl0 + 2;
    const bool todd = (t & 1);

    // ---- hoist K fragments: loaded once, reused by all 4 mi tiles ----
    uint32_t kf[4][7][2];
#pragma unroll
    for (int ni = 0; ni < 7; ++ni) {
        int kr = 8 * ni + g; if (kr > 48) kr = 48;
        const float* kp = kbase + (size_t)kr * 768;
#pragma unroll
        for (int k = 0; k < 4; ++k) {
            kf[k][ni][0] = __float_as_uint(kp[8 * k + t]);
            kf[k][ni][1] = __float_as_uint(kp[8 * k + t + 4]);
        }
    }

#pragma unroll
    for (int mi = 0; mi < 4; ++mi) {
        const int r0 = 16 * mi + g;
        const int r1 = r0 + 8;
        const int r0c = r0 < 48 ? r0 : 48;
        const int r1c = r1 < 48 ? r1 : 48;
        const float* qr0 = qbase + (size_t)r0c * 768;
        const float* qr1 = qbase + (size_t)r1c * 768;

        // ---- S = Q K^T ----
        float S[7][4];
#pragma unroll
        for (int ni = 0; ni < 7; ++ni) {
            S[ni][0] = 0.f; S[ni][1] = 0.f; S[ni][2] = 0.f; S[ni][3] = 0.f;
        }
#pragma unroll
        for (int k = 0; k < 4; ++k) {
            const int kk = 8 * k;
            const uint32_t a0 = __float_as_uint(qr0[kk + t]);
            const uint32_t a1 = __float_as_uint(qr1[kk + t]);
            const uint32_t a2 = __float_as_uint(qr0[kk + t + 4]);
            const uint32_t a3 = __float_as_uint(qr1[kk + t + 4]);
#pragma unroll
            for (int ni = 0; ni < 7; ++ni)
                mma_tf32(S[ni], a0, a1, a2, a3, kf[k][ni][0], kf[k][ni][1]);
        }

        // ---- softmax in C-fragments ----
        float sum0 = 0.f, sum1 = 0.f;
        const float* bm0 = bmp + r0c * BMSTR;
        const float* bm1 = bmp + r1c * BMSTR;
#pragma unroll
        for (int ni = 0; ni < 7; ++ni) {
            const int c = 8 * ni + 2 * t;
            const float2 m0 = *(const float2*)(bm0 + c);
            const float2 m1 = *(const float2*)(bm1 + c);
            float e0 = 0.f, e1 = 0.f, e2 = 0.f, e3 = 0.f;
            if (c < LTOK)     { e0 = fastexp(S[ni][0] + m0.x); e2 = fastexp(S[ni][2] + m1.x); }
            if (c + 1 < LTOK) { e1 = fastexp(S[ni][1] + m0.y); e3 = fastexp(S[ni][3] + m1.y); }
            S[ni][0] = e0; S[ni][1] = e1; S[ni][2] = e2; S[ni][3] = e3;
            sum0 += e0 + e1; sum1 += e2 + e3;
        }
        sum0 += __shfl_xor_sync(0xffffffffu, sum0, 1);
        sum0 += __shfl_xor_sync(0xffffffffu, sum0, 2);
        sum1 += __shfl_xor_sync(0xffffffffu, sum1, 1);
        sum1 += __shfl_xor_sync(0xffffffffu, sum1, 2);
        const float inv0 = 1.f / sum0, inv1 = 1.f / sum1;

#pragma unroll
        for (int ni = 0; ni < 7; ++ni) {
            S[ni][0] = __uint_as_float(f2tf32(S[ni][0] * inv0));
            S[ni][1] = __uint_as_float(f2tf32(S[ni][1] * inv0));
            S[ni][2] = __uint_as_float(f2tf32(S[ni][2] * inv1));
            S[ni][3] = __uint_as_float(f2tf32(S[ni][3] * inv1));
        }

        // ---- O = P V ----
        float O[4][4];
#pragma unroll
        for (int nv = 0; nv < 4; ++nv) {
            O[nv][0] = 0.f; O[nv][1] = 0.f; O[nv][2] = 0.f; O[nv][3] = 0.f;
        }
#pragma unroll
        for (int kt = 0; kt < 7; ++kt) {
            const float v00 = __shfl_sync(0xffffffffu, S[kt][0], sl0);
            const float v01 = __shfl_sync(0xffffffffu, S[kt][1], sl0);
            const float v20 = __shfl_sync(0xffffffffu, S[kt][0], sl2);
            const float v21 = __shfl_sync(0xffffffffu, S[kt][1], sl2);
            const float v10 = __shfl_sync(0xffffffffu, S[kt][2], sl0);
            const float v11 = __shfl_sync(0xffffffffu, S[kt][3], sl0);
            const float v30 = __shfl_sync(0xffffffffu, S[kt][2], sl2);
            const float v31 = __shfl_sync(0xffffffffu, S[kt][3], sl2);
            const uint32_t a0 = __float_as_uint(todd ? v01 : v00);
            const uint32_t a2 = __float_as_uint(todd ? v21 : v20);
            const uint32_t a1 = __float_as_uint(todd ? v11 : v10);
            const uint32_t a3 = __float_as_uint(todd ? v31 : v30);

            int vr0 = 8 * kt + t;     if (vr0 > 48) vr0 = 48;
            int vr1 = 8 * kt + t + 4; if (vr1 > 48) vr1 = 48;
            const float* vp0 = vbase + (size_t)vr0 * 768;
            const float* vp1 = vbase + (size_t)vr1 * 768;
#pragma unroll
            for (int nv = 0; nv < 4; ++nv) {
                const uint32_t b0 = __float_as_uint(vp0[8 * nv + g]);
                const uint32_t b1 = __float_as_uint(vp1[8 * nv + g]);
                mma_tf32(O[nv], a0, a1, a2, a3, b0, b1);
            }
        }

        // ---- store O rounded (feeds GEMM2 as pre-rounded A) ----
        float* orow0 = g_attn + ((size_t)n * LTOK + r0) * CDIM + h * 32;
        float* orow1 = g_attn + ((size_t)n * LTOK + r1) * CDIM + h * 32;
#pragma unroll
        for (int nv = 0; nv < 4; ++nv) {
            const int c = 8 * nv + 2 * t;
            if (r0 < LTOK)
                *(float2*)(orow0 + c) = make_float2(__uint_as_float(f2tf32(O[nv][0])),
                                                    __uint_as_float(f2tf32(O[nv][1])));
            if (r1 < LTOK)
                *(float2*)(orow1 + c) = make_float2(__uint_as_float(f2tf32(O[nv][2])),
                                                    __uint_as_float(f2tf32(O[nv][3])));
        }
    }
}

// ---------------- launch ----------------
extern "C" void kernel_launch(void* const* d_in, const int* in_sizes, int n_in,
                              void* d_out, int out_size)
{
    const float* x    = (const float*)d_in[0];
    const float* mask = (const float*)d_in[1];
    const float* wq   = (const float*)d_in[2];
    const float* wk   = (const float*)d_in[3];
    const float* wv   = (const float*)d_in[4];
    const float* wo   = (const float*)d_in[5];
    const float* bt   = (const float*)d_in[6];
    const int*   ri   = (const int*)d_in[7];
    float* out = (float*)d_out;

    const int nwin = in_sizes[0] / (LTOK * CDIM);   // 4096
    const int nw   = in_sizes[1] / (LTOK * LTOK);   // 64
    const int M    = nwin * LTOK;                   // 200704 (mult of 128)

    float *xt, *qkv, *attn, *wqkv, *wop;
    cudaGetSymbolAddress((void**)&xt,   g_xt);
    cudaGetSymbolAddress((void**)&qkv,  g_qkv);
    cudaGetSymbolAddress((void**)&attn, g_attn);
    cudaGetSymbolAddress((void**)&wqkv, g_wqkv);
    cudaGetSymbolAddress((void**)&wop,  g_wo);

    cudaFuncSetAttribute((const void*)gemm_cp_kernel<true>,
                         cudaFuncAttributeMaxDynamicSharedMemorySize, SMEM_GEMM);
    cudaFuncSetAttribute((const void*)gemm_cp_kernel<false>,
                         cudaFuncAttributeMaxDynamicSharedMemorySize, SMEM_GEMM);

    // 1) pre-round inputs + fuse bias/mask
    cvt_x_kernel<<<(M * CDIM / 4) / 256, 256>>>(x);
    pack_w_kernel<<<128, 256>>>(wq, wk, wv, wo);   // FIXED: 64 wqkv + 64 wo blocks
    dim3 gb(nw, NHEAD);
    bm_kernel<<<gb, 256>>>(mask, bt, ri);

    // 2) QKV projection (rounded output)
    dim3 g1(768 / BN, M / BM);
    gemm_cp_kernel<true><<<g1, 256, SMEM_GEMM>>>(xt, wqkv, qkv, M, 256, 768, 768);

    // 3) attention
    attn_kernel<<<nwin, 256>>>(nw);

    // 4) output projection (fp32 output)
    dim3 g3(256 / BN, M / BM);
    gemm_cp_kernel<false><<<g3, 256, SMEM_GEMM>>>(attn, wop, out, M, 256, 256, 256);
}

// round 13
// speedup vs baseline: 1.5858x; 1.5858x over previous
#include <cuda_runtime.h>
#include <cuda_fp16.h>
#include <cstdint>

#define LTOK 49
#define CDIM 256
#define NHEAD 8
#define MAXWIN 4096
#define MAXM (MAXWIN * LTOK)
#define MAXNW 64
#define LL (LTOK * LTOK)
#define BMSTR 50
#define BMLL (LTOK * BMSTR)

// ---------------- scratch ----------------
__device__ alignas(256) __half g_xh[(size_t)MAXM * CDIM];
__device__ alignas(256) __half g_qkvh[(size_t)MAXM * 768];
__device__ alignas(256) __half g_attnh[(size_t)MAXM * CDIM];
__device__ alignas(256) __half g_wqkvh[768 * 256];   // transposed [n][k]
__device__ alignas(256) __half g_woh[256 * 256];     // transposed [n][k]
__device__ alignas(256) float  g_bm[(size_t)MAXNW * NHEAD * BMLL];

// ---------------- helpers ----------------
__device__ __forceinline__ void mma_f16(float acc[4], uint32_t a0, uint32_t a1,
                                        uint32_t a2, uint32_t a3,
                                        uint32_t b0, uint32_t b1) {
    asm volatile("mma.sync.aligned.m16n8k16.row.col.f32.f16.f16.f32 "
        "{%0,%1,%2,%3}, {%4,%5,%6,%7}, {%8,%9}, {%0,%1,%2,%3};"
        : "+f"(acc[0]), "+f"(acc[1]), "+f"(acc[2]), "+f"(acc[3])
        : "r"(a0), "r"(a1), "r"(a2), "r"(a3), "r"(b0), "r"(b1));
}
__device__ __forceinline__ uint32_t ldh2(const __half* p) {
    return *(const uint32_t*)p;
}
__device__ __forceinline__ uint32_t packh2(float a, float b) {
    __half2 h = __floats2half2_rn(a, b);
    return *(uint32_t*)&h;
}
__device__ __forceinline__ float fastexp(float x) {
    x = fmaxf(x, -80.f);
    const float LOG2E = 1.4426950408889634f, MAGIC = 12582912.f;
    float z = fmaf(x, LOG2E, MAGIC);
    float f = fmaf(x, LOG2E, MAGIC - z);
    float p = 0.0013333558f;
    p = fmaf(p, f, 0.0096181291f); p = fmaf(p, f, 0.0555041087f);
    p = fmaf(p, f, 0.2402265069f); p = fmaf(p, f, 0.6931471806f);
    p = fmaf(p, f, 1.0f);
    return __int_as_float(__float_as_int(p) + (__float_as_int(z) << 23));
}

// ---------------- prep kernels ----------------
// x -> half. one thread = 8 floats -> 8 halfs (uint4)
__global__ void cvt_x_kernel(const float* __restrict__ x) {
    const size_t i = (size_t)blockIdx.x * 256 + threadIdx.x;
    const float4 v0 = ((const float4*)x)[2 * i];
    const float4 v1 = ((const float4*)x)[2 * i + 1];
    uint4 u;
    u.x = packh2(v0.x, v0.y); u.y = packh2(v0.z, v0.w);
    u.z = packh2(v1.x, v1.y); u.w = packh2(v1.z, v1.w);
    ((uint4*)g_xh)[i] = u;
}
// weights: transpose + half. block = output row n (0..1023), thread = k
__global__ void pack_w_kernel(const float* __restrict__ wq, const float* __restrict__ wk,
                              const float* __restrict__ wv, const float* __restrict__ wo) {
    const int b = blockIdx.x, t = threadIdx.x;
    const float* src; int col; __half* dst;
    if (b < 256)      { src = wq; col = b;       dst = g_wqkvh + (size_t)b * 256; }
    else if (b < 512) { src = wk; col = b - 256; dst = g_wqkvh + (size_t)b * 256; }
    else if (b < 768) { src = wv; col = b - 512; dst = g_wqkvh + (size_t)b * 256; }
    else              { src = wo; col = b - 768; dst = g_woh + (size_t)(b - 768) * 256; }
    dst[t] = __float2half_rn(src[(size_t)t * 256 + col]);
}
__global__ void bm_kernel(const float* __restrict__ mask, const float* __restrict__ bias_table,
                          const int* __restrict__ rel_index) {
    const int w = blockIdx.x, h = blockIdx.y;
    const float* mp = mask + (size_t)w * LL;
    float* dst = g_bm + ((size_t)w * NHEAD + h) * BMLL;
    for (int e = threadIdx.x; e < BMLL; e += 256) {
        const int i = e / BMSTR, j = e % BMSTR;
        dst[e] = (j < LTOK) ? bias_table[rel_index[i * LTOK + j] * NHEAD + h] + mp[i * LTOK + j] : 0.f;
    }
}

// ---------------- fp16 GEMM: C[M,N] = A[M,256] @ Wt^T (Wt=[N][256]) ----------
// BM=BN=128, BK=32 halfs. 8 warps (2x4), warp tile 64x32. Single-buffer staging.
#define ASTRH 40
__global__ void __launch_bounds__(256, 2)
gemm_h_kernel(const __half* __restrict__ A, const __half* __restrict__ Wt,
              __half* __restrict__ Ch, float* __restrict__ Cf, int ldc)
{
    __shared__ __align__(16) __half As[128 * ASTRH];   // 10240 B
    __shared__ __align__(16) __half Bs[128 * ASTRH];   // 10240 B  (Bs[n][k])

    const int bn = blockIdx.x, bm = blockIdx.y;
    const int tid = threadIdx.x;
    const int lane = tid & 31, warp = tid >> 5;
    const int wm = warp >> 2, wn = warp & 3;
    const int g = lane >> 2, t = lane & 3;

    float acc[4][4][4];
#pragma unroll
    for (int mi = 0; mi < 4; ++mi)
#pragma unroll
        for (int ni = 0; ni < 4; ++ni)
#pragma unroll
            for (int q = 0; q < 4; ++q) acc[mi][ni][q] = 0.f;

    const __half* Ab = A + (size_t)bm * 128 * 256;
    const __half* Wb = Wt + (size_t)bn * 128 * 256;

    for (int kc = 0; kc < 256; kc += 32) {
        __syncthreads();
#pragma unroll
        for (int it = 0; it < 2; ++it) {
            const int e = tid + it * 256;          // 0..511 uint4 units
            const int r = e >> 2, c16 = e & 3;     // row, 8-half block
            *(uint4*)&As[r * ASTRH + c16 * 8] =
                *(const uint4*)(Ab + (size_t)r * 256 + kc + c16 * 8);
            *(uint4*)&Bs[r * ASTRH + c16 * 8] =
                *(const uint4*)(Wb + (size_t)r * 256 + kc + c16 * 8);
        }
        __syncthreads();

#pragma unroll
        for (int ks = 0; ks < 2; ++ks) {
            const int kb = 16 * ks + 2 * t;
            uint32_t a[4][4];
#pragma unroll
            for (int mi = 0; mi < 4; ++mi) {
                const __half* ap = &As[(wm * 64 + mi * 16 + g) * ASTRH + kb];
                a[mi][0] = ldh2(ap);
                a[mi][2] = ldh2(ap + 8);
                a[mi][1] = ldh2(ap + 8 * ASTRH);
                a[mi][3] = ldh2(ap + 8 * ASTRH + 8);
            }
            uint32_t b[4][2];
#pragma unroll
            for (int ni = 0; ni < 4; ++ni) {
                const __half* bp = &Bs[(wn * 32 + ni * 8 + g) * ASTRH + kb];
                b[ni][0] = ldh2(bp);
                b[ni][1] = ldh2(bp + 8);
            }
#pragma unroll
            for (int mi = 0; mi < 4; ++mi)
#pragma unroll
                for (int ni = 0; ni < 4; ++ni)
                    mma_f16(acc[mi][ni], a[mi][0], a[mi][1], a[mi][2], a[mi][3],
                            b[ni][0], b[ni][1]);
        }
    }

    // epilogue
#pragma unroll
    for (int mi = 0; mi < 4; ++mi) {
        const size_t r0 = (size_t)bm * 128 + wm * 64 + mi * 16 + g;
#pragma unroll
        for (int ni = 0; ni < 4; ++ni) {
            const int col = bn * 128 + wn * 32 + ni * 8 + 2 * t;
            if (Ch) {
                *(__half2*)&Ch[r0 * ldc + col] =
                    __floats2half2_rn(acc[mi][ni][0], acc[mi][ni][1]);
                *(__half2*)&Ch[(r0 + 8) * ldc + col] =
                    __floats2half2_rn(acc[mi][ni][2], acc[mi][ni][3]);
            } else {
                *(float2*)&Cf[r0 * ldc + col] = make_float2(acc[mi][ni][0], acc[mi][ni][1]);
                *(float2*)&Cf[(r0 + 8) * ldc + col] = make_float2(acc[mi][ni][2], acc[mi][ni][3]);
            }
        }
    }
}

// ---------------- attention: fp16 m16n8k16, shuffle-free P->A ----------------
__global__ void __launch_bounds__(256)
attn_kernel(int nw)
{
    const int n = blockIdx.x;
    const int h = threadIdx.x >> 5;
    const int lane = threadIdx.x & 31;
    const int g = lane >> 2, t = lane & 3;

    const __half* qb = g_qkvh + (size_t)n * LTOK * 768 + h * 32;
    const __half* kb = qb + 256;
    const __half* vb = qb + 512;
    const float* bmp = g_bm + ((size_t)(n % nw) * NHEAD + h) * BMLL;

    // K fragments (mi-invariant): kf[ks][ni][2]
    uint32_t kf[2][7][2];
#pragma unroll
    for (int ni = 0; ni < 7; ++ni) {
        int kr = 8 * ni + g; if (kr > 48) kr = 48;
        const __half* kp = kb + (size_t)kr * 768;
#pragma unroll
        for (int ks = 0; ks < 2; ++ks) {
            kf[ks][ni][0] = ldh2(kp + 16 * ks + 2 * t);
            kf[ks][ni][1] = ldh2(kp + 16 * ks + 2 * t + 8);
        }
    }
    // V fragments (mi-invariant): vf[kt][nv][2]; pairs along k (rows of V)
    uint32_t vf[4][4][2];
#pragma unroll
    for (int kt = 0; kt < 4; ++kt) {
        int k0 = 16 * kt + 2 * t, k1 = k0 + 8;
        int k0a = k0 < 48 ? k0 : 48, k0b = k0 + 1 < 48 ? k0 + 1 : 48;
        int k1a = k1 < 48 ? k1 : 48, k1b = k1 + 1 < 48 ? k1 + 1 : 48;
#pragma unroll
        for (int nv = 0; nv < 4; ++nv) {
            const int col = 8 * nv + g;
            vf[kt][nv][0] = packh2(__half2float(vb[(size_t)k0a * 768 + col]),
                                   __half2float(vb[(size_t)k0b * 768 + col]));
            vf[kt][nv][1] = packh2(__half2float(vb[(size_t)k1a * 768 + col]),
                                   __half2float(vb[(size_t)k1b * 768 + col]));
        }
    }

#pragma unroll
    for (int mi = 0; mi < 4; ++mi) {
        const int r0 = 16 * mi + g, r1 = r0 + 8;
        const int r0c = r0 < 48 ? r0 : 48, r1c = r1 < 48 ? r1 : 48;
        const __half* qr0 = qb + (size_t)r0c * 768;
        const __half* qr1 = qb + (size_t)r1c * 768;

        // S = Q K^T
        float S[7][4];
#pragma unroll
        for (int ni = 0; ni < 7; ++ni) { S[ni][0] = S[ni][1] = S[ni][2] = S[ni][3] = 0.f; }
#pragma unroll
        for (int ks = 0; ks < 2; ++ks) {
            const int kb16 = 16 * ks + 2 * t;
            const uint32_t a0 = ldh2(qr0 + kb16);
            const uint32_t a1 = ldh2(qr1 + kb16);
            const uint32_t a2 = ldh2(qr0 + kb16 + 8);
            const uint32_t a3 = ldh2(qr1 + kb16 + 8);
#pragma unroll
            for (int ni = 0; ni < 7; ++ni)
                mma_f16(S[ni], a0, a1, a2, a3, kf[ks][ni][0], kf[ks][ni][1]);
        }

        // softmax in fragments (scores bounded -> no max pass)
        float sum0 = 0.f, sum1 = 0.f;
        const float* bm0 = bmp + r0c * BMSTR;
        const float* bm1 = bmp + r1c * BMSTR;
#pragma unroll
        for (int ni = 0; ni < 7; ++ni) {
            const int c = 8 * ni + 2 * t;
            const float2 m0 = *(const float2*)(bm0 + c);
            const float2 m1 = *(const float2*)(bm1 + c);
            float e0 = 0.f, e1 = 0.f, e2 = 0.f, e3 = 0.f;
            if (c < LTOK)     { e0 = fastexp(S[ni][0] + m0.x); e2 = fastexp(S[ni][2] + m1.x); }
            if (c + 1 < LTOK) { e1 = fastexp(S[ni][1] + m0.y); e3 = fastexp(S[ni][3] + m1.y); }
            S[ni][0] = e0; S[ni][1] = e1; S[ni][2] = e2; S[ni][3] = e3;
            sum0 += e0 + e1; sum1 += e2 + e3;
        }
        sum0 += __shfl_xor_sync(0xffffffffu, sum0, 1);
        sum0 += __shfl_xor_sync(0xffffffffu, sum0, 2);
        sum1 += __shfl_xor_sync(0xffffffffu, sum1, 1);
        sum1 += __shfl_xor_sync(0xffffffffu, sum1, 2);
        const float inv0 = 1.f / sum0, inv1 = 1.f / sum1;
#pragma unroll
        for (int ni = 0; ni < 7; ++ni) {
            S[ni][0] *= inv0; S[ni][1] *= inv0;
            S[ni][2] *= inv1; S[ni][3] *= inv1;
        }

        // O = P V : P C-frag pairs ARE fp16 A-frag half2 pairs (no shuffles)
        float O[4][4];
#pragma unroll
        for (int nv = 0; nv < 4; ++nv) { O[nv][0] = O[nv][1] = O[nv][2] = O[nv][3] = 0.f; }
#pragma unroll
        for (int kt = 0; kt < 4; ++kt) {
            const int i0 = 2 * kt, i1 = 2 * kt + 1;
            const uint32_t pa0 = packh2(S[i0][0], S[i0][1]);
            const uint32_t pa1 = packh2(S[i0][2], S[i0][3]);
            const uint32_t pa2 = (i1 < 7) ? packh2(S[i1][0], S[i1][1]) : 0u;
            const uint32_t pa3 = (i1 < 7) ? packh2(S[i1][2], S[i1][3]) : 0u;
#pragma unroll
            for (int nv = 0; nv < 4; ++nv)
                mma_f16(O[nv], pa0, pa1, pa2, pa3, vf[kt][nv][0], vf[kt][nv][1]);
        }

        // store O (half, feeds GEMM2)
        __half* orow0 = g_attnh + ((size_t)n * LTOK + r0) * CDIM + h * 32;
        __half* orow1 = g_attnh + ((size_t)n * LTOK + r1) * CDIM + h * 32;
#pragma unroll
        for (int nv = 0; nv < 4; ++nv) {
            const int c = 8 * nv + 2 * t;
            if (r0 < LTOK) *(__half2*)(orow0 + c) = __floats2half2_rn(O[nv][0], O[nv][1]);
            if (r1 < LTOK) *(__half2*)(orow1 + c) = __floats2half2_rn(O[nv][2], O[nv][3]);
        }
    }
}

// ---------------- launch ----------------
extern "C" void kernel_launch(void* const* d_in, const int* in_sizes, int n_in,
                              void* d_out, int out_size)
{
    const float* x    = (const float*)d_in[0];
    const float* mask = (const float*)d_in[1];
    const float* wq   = (const float*)d_in[2];
    const float* wk   = (const float*)d_in[3];
    const float* wv   = (const float*)d_in[4];
    const float* wo   = (const float*)d_in[5];
    const float* bt   = (const float*)d_in[6];
    const int*   ri   = (const int*)d_in[7];
    float* out = (float*)d_out;

    const int nwin = in_sizes[0] / (LTOK * CDIM);   // 4096
    const int nw   = in_sizes[1] / (LTOK * LTOK);   // 64
    const int M    = nwin * LTOK;                   // 200704 = 128*1568

    __half *xh, *qkvh, *attnh, *wqkvh, *woh;
    cudaGetSymbolAddress((void**)&xh,    g_xh);
    cudaGetSymbolAddress((void**)&qkvh,  g_qkvh);
    cudaGetSymbolAddress((void**)&attnh, g_attnh);
    cudaGetSymbolAddress((void**)&wqkvh, g_wqkvh);
    cudaGetSymbolAddress((void**)&woh,   g_woh);

    // prep
    cvt_x_kernel<<<(M * CDIM / 8) / 256, 256>>>(x);
    pack_w_kernel<<<1024, 256>>>(wq, wk, wv, wo);
    dim3 gb(nw, NHEAD);
    bm_kernel<<<gb, 256>>>(mask, bt, ri);

    // QKV projection -> half
    dim3 g1(6, M / 128);
    gemm_h_kernel<<<g1, 256>>>(xh, wqkvh, qkvh, nullptr, 768);

    // attention
    attn_kernel<<<nwin, 256>>>(nw);

    // output projection -> float
    dim3 g3(2, M / 128);
    gemm_h_kernel<<<g3, 256>>>(attnh, woh, nullptr, out, 256);
}

// round 15
// speedup vs baseline: 1.9466x; 1.2275x over previous
#include <cuda_runtime.h>
#include <cuda_fp16.h>
#include <cstdint>

#define LTOK 49
#define CDIM 256
#define NHEAD 8
#define MAXWIN 4096
#define MAXM (MAXWIN * LTOK)
#define MAXNW 64
#define LL (LTOK * LTOK)
#define BMSTR 50
#define BMLL (LTOK * BMSTR)

// ---------------- scratch ----------------
__device__ alignas(256) __half g_xh[(size_t)MAXM * CDIM];
__device__ alignas(256) __half g_qkvh[(size_t)MAXM * 768];
__device__ alignas(256) __half g_attnh[(size_t)MAXM * CDIM];
__device__ alignas(256) __half g_wqkvh[768 * 256];   // transposed [n][k]
__device__ alignas(256) __half g_woh[256 * 256];     // transposed [n][k]
__device__ alignas(256) float  g_bm[(size_t)MAXNW * NHEAD * BMLL];

// ---------------- helpers ----------------
__device__ __forceinline__ void mma_f16(float acc[4], uint32_t a0, uint32_t a1,
                                        uint32_t a2, uint32_t a3,
                                        uint32_t b0, uint32_t b1) {
    asm volatile("mma.sync.aligned.m16n8k16.row.col.f32.f16.f16.f32 "
        "{%0,%1,%2,%3}, {%4,%5,%6,%7}, {%8,%9}, {%0,%1,%2,%3};"
        : "+f"(acc[0]), "+f"(acc[1]), "+f"(acc[2]), "+f"(acc[3])
        : "r"(a0), "r"(a1), "r"(a2), "r"(a3), "r"(b0), "r"(b1));
}
__device__ __forceinline__ uint32_t ldh2(const __half* p) { return *(const uint32_t*)p; }
__device__ __forceinline__ uint32_t packh2(float a, float b) {
    __half2 h = __floats2half2_rn(a, b);
    return *(uint32_t*)&h;
}
__device__ __forceinline__ uint32_t smem_u32(const void* p) {
    return (uint32_t)__cvta_generic_to_shared(p);
}
#define CPASYNC16(dst, src) \
    asm volatile("cp.async.ca.shared.global [%0], [%1], 16;" :: "r"(dst), "l"(src))
__device__ __forceinline__ float fastexp(float x) {
    x = fmaxf(x, -80.f);
    const float LOG2E = 1.4426950408889634f, MAGIC = 12582912.f;
    float z = fmaf(x, LOG2E, MAGIC);
    float f = fmaf(x, LOG2E, MAGIC - z);
    float p = 0.0013333558f;
    p = fmaf(p, f, 0.0096181291f); p = fmaf(p, f, 0.0555041087f);
    p = fmaf(p, f, 0.2402265069f); p = fmaf(p, f, 0.6931471806f);
    p = fmaf(p, f, 1.0f);
    return __int_as_float(__float_as_int(p) + (__float_as_int(z) << 23));
}

// ---------------- prep kernels (unchanged) ----------------
__global__ void cvt_x_kernel(const float* __restrict__ x) {
    const size_t i = (size_t)blockIdx.x * 256 + threadIdx.x;
    const float4 v0 = ((const float4*)x)[2 * i];
    const float4 v1 = ((const float4*)x)[2 * i + 1];
    uint4 u;
    u.x = packh2(v0.x, v0.y); u.y = packh2(v0.z, v0.w);
    u.z = packh2(v1.x, v1.y); u.w = packh2(v1.z, v1.w);
    ((uint4*)g_xh)[i] = u;
}
__global__ void pack_w_kernel(const float* __restrict__ wq, const float* __restrict__ wk,
                              const float* __restrict__ wv, const float* __restrict__ wo) {
    const int b = blockIdx.x, t = threadIdx.x;
    const float* src; int col; __half* dst;
    if (b < 256)      { src = wq; col = b;       dst = g_wqkvh + (size_t)b * 256; }
    else if (b < 512) { src = wk; col = b - 256; dst = g_wqkvh + (size_t)b * 256; }
    else if (b < 768) { src = wv; col = b - 512; dst = g_wqkvh + (size_t)b * 256; }
    else              { src = wo; col = b - 768; dst = g_woh + (size_t)(b - 768) * 256; }
    dst[t] = __float2half_rn(src[(size_t)t * 256 + col]);
}
__global__ void bm_kernel(const float* __restrict__ mask, const float* __restrict__ bias_table,
                          const int* __restrict__ rel_index) {
    const int w = blockIdx.x, h = blockIdx.y;
    const float* mp = mask + (size_t)w * LL;
    float* dst = g_bm + ((size_t)w * NHEAD + h) * BMLL;
    for (int e = threadIdx.x; e < BMLL; e += 256) {
        const int i = e / BMSTR, j = e % BMSTR;
        dst[e] = (j < LTOK) ? bias_table[rel_index[i * LTOK + j] * NHEAD + h] + mp[i * LTOK + j] : 0.f;
    }
}

// ---------------- fp16 GEMM, cp.async double-buffered, BK=64 ----------------
// C[M,N] = A[M,256] @ Wt^T (Wt=[N][256] K-major). BM=BN=128. 8 warps (2x4).
#define ASTRH 72
#define BUF_H (128 * ASTRH)                 // halfs per matrix buffer
#define SMEM_GH (4 * BUF_H * 2)             // A×2 + B×2 = 73728 B

__global__ void __launch_bounds__(256, 2)
gemm_h_kernel(const __half* __restrict__ A, const __half* __restrict__ Wt,
              __half* __restrict__ Ch, float* __restrict__ Cf, int ldc)
{
    extern __shared__ __align__(16) __half smh[];
    __half* As[2] = { smh,             smh + BUF_H };
    __half* Bs[2] = { smh + 2 * BUF_H, smh + 3 * BUF_H };

    const int bn = blockIdx.x, bm = blockIdx.y;
    const int tid = threadIdx.x;
    const int lane = tid & 31, warp = tid >> 5;
    const int wm = warp >> 2, wn = warp & 3;
    const int g = lane >> 2, t = lane & 3;

    const __half* Ab = A + (size_t)bm * 128 * 256;
    const __half* Wb = Wt + (size_t)bn * 128 * 256;

    // staging coordinates: 1024 16B-ops per matrix per chunk, 4 per thread
    const int sr[4] = { tid >> 3, (tid + 256) >> 3, (tid + 512) >> 3, (tid + 768) >> 3 };
    const int sc = (tid & 7) * 8;           // half offset within row
    uint32_t adst[2][4], bdst[2][4];
#pragma unroll
    for (int s = 0; s < 2; ++s)
#pragma unroll
        for (int it = 0; it < 4; ++it) {
            adst[s][it] = smem_u32(&As[s][sr[it] * ASTRH + sc]);
            bdst[s][it] = smem_u32(&Bs[s][sr[it] * ASTRH + sc]);
        }

    float acc[4][4][4];
#pragma unroll
    for (int mi = 0; mi < 4; ++mi)
#pragma unroll
        for (int ni = 0; ni < 4; ++ni)
#pragma unroll
            for (int q = 0; q < 4; ++q) acc[mi][ni][q] = 0.f;

    // prologue: chunk 0 -> buf 0
#pragma unroll
    for (int it = 0; it < 4; ++it) {
        CPASYNC16(adst[0][it], Ab + (size_t)sr[it] * 256 + sc);
        CPASYNC16(bdst[0][it], Wb + (size_t)sr[it] * 256 + sc);
    }
    asm volatile("cp.async.commit_group;" ::: "memory");

    for (int c = 0; c < 4; ++c) {
        const int s = c & 1;
        asm volatile("cp.async.wait_group 0;" ::: "memory");
        __syncthreads();            // staged data visible; prior compute on s done
        if (c + 1 < 4) {
            const int kc = (c + 1) * 64;
            const int s1 = s ^ 1;
#pragma unroll
            for (int it = 0; it < 4; ++it) {
                CPASYNC16(adst[s1][it], Ab + (size_t)sr[it] * 256 + kc + sc);
                CPASYNC16(bdst[s1][it], Wb + (size_t)sr[it] * 256 + kc + sc);
            }
            asm volatile("cp.async.commit_group;" ::: "memory");
        }
        const __half* Asb = As[s];
        const __half* Bsb = Bs[s];
#pragma unroll
        for (int ks = 0; ks < 4; ++ks) {
            const int kb = 16 * ks + 2 * t;
            uint32_t a[4][4];
#pragma unroll
            for (int mi = 0; mi < 4; ++mi) {
                const __half* ap = &Asb[(wm * 64 + mi * 16 + g) * ASTRH + kb];
                a[mi][0] = ldh2(ap);
                a[mi][2] = ldh2(ap + 8);
                a[mi][1] = ldh2(ap + 8 * ASTRH);
                a[mi][3] = ldh2(ap + 8 * ASTRH + 8);
            }
            uint32_t b[4][2];
#pragma unroll
            for (int ni = 0; ni < 4; ++ni) {
                const __half* bp = &Bsb[(wn * 32 + ni * 8 + g) * ASTRH + kb];
                b[ni][0] = ldh2(bp);
                b[ni][1] = ldh2(bp + 8);
            }
#pragma unroll
            for (int mi = 0; mi < 4; ++mi)
#pragma unroll
                for (int ni = 0; ni < 4; ++ni)
                    mma_f16(acc[mi][ni], a[mi][0], a[mi][1], a[mi][2], a[mi][3],
                            b[ni][0], b[ni][1]);
        }
    }

    // epilogue
#pragma unroll
    for (int mi = 0; mi < 4; ++mi) {
        const size_t r0 = (size_t)bm * 128 + wm * 64 + mi * 16 + g;
#pragma unroll
        for (int ni = 0; ni < 4; ++ni) {
            const int col = bn * 128 + wn * 32 + ni * 8 + 2 * t;
            if (Ch) {
                *(__half2*)&Ch[r0 * ldc + col] =
                    __floats2half2_rn(acc[mi][ni][0], acc[mi][ni][1]);
                *(__half2*)&Ch[(r0 + 8) * ldc + col] =
                    __floats2half2_rn(acc[mi][ni][2], acc[mi][ni][3]);
            } else {
                *(float2*)&Cf[r0 * ldc + col] = make_float2(acc[mi][ni][0], acc[mi][ni][1]);
                *(float2*)&Cf[(r0 + 8) * ldc + col] = make_float2(acc[mi][ni][2], acc[mi][ni][3]);
            }
        }
    }
}

// ---------------- attention (unchanged from round 13) ----------------
__global__ void __launch_bounds__(256)
attn_kernel(int nw)
{
    const int n = blockIdx.x;
    const int h = threadIdx.x >> 5;
    const int lane = threadIdx.x & 31;
    const int g = lane >> 2, t = lane & 3;

    const __half* qb = g_qkvh + (size_t)n * LTOK * 768 + h * 32;
    const __half* kb = qb + 256;
    const __half* vb = qb + 512;
    const float* bmp = g_bm + ((size_t)(n % nw) * NHEAD + h) * BMLL;

    uint32_t kf[2][7][2];
#pragma unroll
    for (int ni = 0; ni < 7; ++ni) {
        int kr = 8 * ni + g; if (kr > 48) kr = 48;
        const __half* kp = kb + (size_t)kr * 768;
#pragma unroll
        for (int ks = 0; ks < 2; ++ks) {
            kf[ks][ni][0] = ldh2(kp + 16 * ks + 2 * t);
            kf[ks][ni][1] = ldh2(kp + 16 * ks + 2 * t + 8);
        }
    }
    uint32_t vf[4][4][2];
#pragma unroll
    for (int kt = 0; kt < 4; ++kt) {
        int k0 = 16 * kt + 2 * t, k1 = k0 + 8;
        int k0a = k0 < 48 ? k0 : 48, k0b = k0 + 1 < 48 ? k0 + 1 : 48;
        int k1a = k1 < 48 ? k1 : 48, k1b = k1 + 1 < 48 ? k1 + 1 : 48;
#pragma unroll
        for (int nv = 0; nv < 4; ++nv) {
            const int col = 8 * nv + g;
            vf[kt][nv][0] = packh2(__half2float(vb[(size_t)k0a * 768 + col]),
                                   __half2float(vb[(size_t)k0b * 768 + col]));
            vf[kt][nv][1] = packh2(__half2float(vb[(size_t)k1a * 768 + col]),
                                   __half2float(vb[(size_t)k1b * 768 + col]));
        }
    }

#pragma unroll
    for (int mi = 0; mi < 4; ++mi) {
        const int r0 = 16 * mi + g, r1 = r0 + 8;
        const int r0c = r0 < 48 ? r0 : 48, r1c = r1 < 48 ? r1 : 48;
        const __half* qr0 = qb + (size_t)r0c * 768;
        const __half* qr1 = qb + (size_t)r1c * 768;

        float S[7][4];
#pragma unroll
        for (int ni = 0; ni < 7; ++ni) { S[ni][0] = S[ni][1] = S[ni][2] = S[ni][3] = 0.f; }
#pragma unroll
        for (int ks = 0; ks < 2; ++ks) {
            const int kb16 = 16 * ks + 2 * t;
            const uint32_t a0 = ldh2(qr0 + kb16);
            const uint32_t a1 = ldh2(qr1 + kb16);
            const uint32_t a2 = ldh2(qr0 + kb16 + 8);
            const uint32_t a3 = ldh2(qr1 + kb16 + 8);
#pragma unroll
            for (int ni = 0; ni < 7; ++ni)
                mma_f16(S[ni], a0, a1, a2, a3, kf[ks][ni][0], kf[ks][ni][1]);
        }

        float sum0 = 0.f, sum1 = 0.f;
        const float* bm0 = bmp + r0c * BMSTR;
        const float* bm1 = bmp + r1c * BMSTR;
#pragma unroll
        for (int ni = 0; ni < 7; ++ni) {
            const int c = 8 * ni + 2 * t;
            const float2 m0 = *(const float2*)(bm0 + c);
            const float2 m1 = *(const float2*)(bm1 + c);
            float e0 = 0.f, e1 = 0.f, e2 = 0.f, e3 = 0.f;
            if (c < LTOK)     { e0 = fastexp(S[ni][0] + m0.x); e2 = fastexp(S[ni][2] + m1.x); }
            if (c + 1 < LTOK) { e1 = fastexp(S[ni][1] + m0.y); e3 = fastexp(S[ni][3] + m1.y); }
            S[ni][0] = e0; S[ni][1] = e1; S[ni][2] = e2; S[ni][3] = e3;
            sum0 += e0 + e1; sum1 += e2 + e3;
        }
        sum0 += __shfl_xor_sync(0xffffffffu, sum0, 1);
        sum0 += __shfl_xor_sync(0xffffffffu, sum0, 2);
        sum1 += __shfl_xor_sync(0xffffffffu, sum1, 1);
        sum1 += __shfl_xor_sync(0xffffffffu, sum1, 2);
        const float inv0 = 1.f / sum0, inv1 = 1.f / sum1;
#pragma unroll
        for (int ni = 0; ni < 7; ++ni) {
            S[ni][0] *= inv0; S[ni][1] *= inv0;
            S[ni][2] *= inv1; S[ni][3] *= inv1;
        }

        float O[4][4];
#pragma unroll
        for (int nv = 0; nv < 4; ++nv) { O[nv][0] = O[nv][1] = O[nv][2] = O[nv][3] = 0.f; }
#pragma unroll
        for (int kt = 0; kt < 4; ++kt) {
            const int i0 = 2 * kt, i1 = 2 * kt + 1;
            const uint32_t pa0 = packh2(S[i0][0], S[i0][1]);
            const uint32_t pa1 = packh2(S[i0][2], S[i0][3]);
            const uint32_t pa2 = (i1 < 7) ? packh2(S[i1][0], S[i1][1]) : 0u;
            const uint32_t pa3 = (i1 < 7) ? packh2(S[i1][2], S[i1][3]) : 0u;
#pragma unroll
            for (int nv = 0; nv < 4; ++nv)
                mma_f16(O[nv], pa0, pa1, pa2, pa3, vf[kt][nv][0], vf[kt][nv][1]);
        }

        __half* orow0 = g_attnh + ((size_t)n * LTOK + r0) * CDIM + h * 32;
        __half* orow1 = g_attnh + ((size_t)n * LTOK + r1) * CDIM + h * 32;
#pragma unroll
        for (int nv = 0; nv < 4; ++nv) {
            const int c = 8 * nv + 2 * t;
            if (r0 < LTOK) *(__half2*)(orow0 + c) = __floats2half2_rn(O[nv][0], O[nv][1]);
            if (r1 < LTOK) *(__half2*)(orow1 + c) = __floats2half2_rn(O[nv][2], O[nv][3]);
        }
    }
}

// ---------------- launch ----------------
extern "C" void kernel_launch(void* const* d_in, const int* in_sizes, int n_in,
                              void* d_out, int out_size)
{
    const float* x    = (const float*)d_in[0];
    const float* mask = (const float*)d_in[1];
    const float* wq   = (const float*)d_in[2];
    const float* wk   = (const float*)d_in[3];
    const float* wv   = (const float*)d_in[4];
    const float* wo   = (const float*)d_in[5];
    const float* bt   = (const float*)d_in[6];
    const int*   ri   = (const int*)d_in[7];
    float* out = (float*)d_out;

    const int nwin = in_sizes[0] / (LTOK * CDIM);   // 4096
    const int nw   = in_sizes[1] / (LTOK * LTOK);   // 64
    const int M    = nwin * LTOK;                   // 200704 = 128*1568

    __half *xh, *qkvh, *attnh, *wqkvh, *woh;
    cudaGetSymbolAddress((void**)&xh,    g_xh);
    cudaGetSymbolAddress((void**)&qkvh,  g_qkvh);
    cudaGetSymbolAddress((void**)&attnh, g_attnh);
    cudaGetSymbolAddress((void**)&wqkvh, g_wqkvh);
    cudaGetSymbolAddress((void**)&woh,   g_woh);

    cudaFuncSetAttribute((const void*)gemm_h_kernel,
                         cudaFuncAttributeMaxDynamicSharedMemorySize, SMEM_GH);

    // prep
    cvt_x_kernel<<<(M * CDIM / 8) / 256, 256>>>(x);
    pack_w_kernel<<<1024, 256>>>(wq, wk, wv, wo);
    dim3 gb(nw, NHEAD);
    bm_kernel<<<gb, 256>>>(mask, bt, ri);

    // QKV projection -> half
    dim3 g1(6, M / 128);
    gemm_h_kernel<<<g1, 256, SMEM_GH>>>(xh, wqkvh, qkvh, nullptr, 768);

    // attention
    attn_kernel<<<nwin, 256>>>(nw);

    // output projection -> float
    dim3 g3(2, M / 128);
    gemm_h_kernel<<<g3, 256, SMEM_GH>>>(attnh, woh, nullptr, out, 256);
}